// round 1
// baseline (speedup 1.0000x reference)
#include <cuda_runtime.h>

// ---------------------------------------------------------------------------
// Problem constants (fixed by the dataset): B=4, E=400000, N_NODES=50000,
// N_REL=500, D=64, D_LG=256, K_PER_VI=20, N_MEM=131072.
// Scratch for projected tables (device globals: no allocation allowed).
// ---------------------------------------------------------------------------
__device__ float g_hc[131072 * 64];   // tanh(hidden_con @ Wc + bc)
__device__ float g_hu[50000 * 64];    // tanh(hidden_uncon @ Wu + bu)

// ---------------- packed f32x2 helpers (sm_103a) ----------------
__device__ __forceinline__ unsigned long long pack2(float x, float y) {
    unsigned long long u;
    asm("mov.b64 %0, {%1,%2};" : "=l"(u) : "f"(x), "f"(y));
    return u;
}
__device__ __forceinline__ void unpack2(unsigned long long u, float& x, float& y) {
    asm("mov.b64 {%0,%1}, %2;" : "=f"(x), "=f"(y) : "l"(u));
}
__device__ __forceinline__ void fma2(unsigned long long& d,
                                     unsigned long long a, unsigned long long b) {
    asm("fma.rn.f32x2 %0, %1, %2, %0;" : "+l"(d) : "l"(a), "l"(b));
}

__device__ __forceinline__ float tanh_fast(float x) {
    float e = __expf(-2.0f * fabsf(x));
    float t = (1.0f - e) / (1.0f + e);
    return copysignf(t, x);
}

// ---------------------------------------------------------------------------
// Projection: out[row, 0:64] = tanh(X[row, 0:K] @ W[K,64] + bias)
// BM=256 rows/block, 256 threads, thread tile = 4 rows x 16 cols (8 f32x2 pairs)
// ---------------------------------------------------------------------------
template <int K>
__global__ void __launch_bounds__(256) proj_tanh_kernel(
    const float* __restrict__ X, const float* __restrict__ W,
    const float* __restrict__ bias, float* __restrict__ out, int rows)
{
    constexpr int BK = 16;
    constexpr int BM = 256;
    __shared__ __align__(16) float Xs[BM][BK + 1];
    __shared__ __align__(16) float Ws[BK][64];

    const int tid = threadIdx.x;
    const int r0  = blockIdx.x * BM;
    const int rr  = (tid >> 2) * 4;       // base row within tile (4 consecutive)
    const int jg  = (tid & 3) * 16;       // base col (16 cols)

    unsigned long long acc[4][8];
#pragma unroll
    for (int r = 0; r < 4; r++)
#pragma unroll
        for (int p = 0; p < 8; p++) acc[r][p] = 0ull;   // +0.0f pair

    for (int k0 = 0; k0 < K; k0 += BK) {
        // load X tile (coalesced 64B row chunks)
#pragma unroll
        for (int i = tid; i < BM * BK; i += 256) {
            int r = i >> 4, c = i & 15;
            int row = r0 + r;
            Xs[r][c] = (row < rows) ? X[(long long)row * K + k0 + c] : 0.0f;
        }
        // load W chunk
#pragma unroll
        for (int i = tid; i < BK * 64; i += 256) {
            Ws[i >> 6][i & 63] = W[(long long)(k0 + (i >> 6)) * 64 + (i & 63)];
        }
        __syncthreads();

#pragma unroll
        for (int kk = 0; kk < BK; kk++) {
            unsigned long long xv[4];
#pragma unroll
            for (int r = 0; r < 4; r++) {
                float x = Xs[rr + r][kk];
                xv[r] = pack2(x, x);
            }
#pragma unroll
            for (int p = 0; p < 8; p++) {
                unsigned long long wv =
                    *reinterpret_cast<const unsigned long long*>(&Ws[kk][jg + 2 * p]);
#pragma unroll
                for (int r = 0; r < 4; r++) fma2(acc[r][p], xv[r], wv);
            }
        }
        __syncthreads();
    }

    // epilogue: bias + tanh + coalesced-ish float4 stores (L2 merges sectors)
    float bvs[16];
#pragma unroll
    for (int j = 0; j < 16; j++) bvs[j] = bias[jg + j];

#pragma unroll
    for (int r = 0; r < 4; r++) {
        int row = r0 + rr + r;
        if (row < rows) {
            float v[16];
#pragma unroll
            for (int p = 0; p < 8; p++) {
                float a, b;
                unpack2(acc[r][p], a, b);
                v[2 * p]     = tanh_fast(a + bvs[2 * p]);
                v[2 * p + 1] = tanh_fast(b + bvs[2 * p + 1]);
            }
            float4* o = reinterpret_cast<float4*>(&out[(long long)row * 64 + jg]);
#pragma unroll
            for (int q = 0; q < 4; q++)
                o[q] = make_float4(v[4 * q], v[4 * q + 1], v[4 * q + 2], v[4 * q + 3]);
        }
    }
}

// ---------------------------------------------------------------------------
// Edge kernel: one block per vi-segment (exactly 20 contiguous edges, vi/eg
// constant within segment). One warp per edge; lane handles dims (2l, 2l+1).
// Computes F-layer logits, segment softmax, and scatters transition*att*y
// directly to out[eg, vj] via atomicAdd (vj-segment sum collapses to this).
// ---------------------------------------------------------------------------
__global__ void __launch_bounds__(640) edge_kernel(
    const float* __restrict__ natt, const int* __restrict__ edges,
    const float* __restrict__ edges_y, const float* __restrict__ rel_table,
    const float* __restrict__ ws, const float* __restrict__ fb,
    const float* __restrict__ out_w, const float* __restrict__ out_b,
    float* __restrict__ out, int n_nodes)
{
    __shared__ __align__(16) float s_ws[8][64];
    __shared__ __align__(16) float s_fb[64];
    __shared__ __align__(16) float s_ow[64];
    __shared__ __align__(16) float s_ob[64];
    __shared__ __align__(16) float s_hu[64];
    __shared__ float s_att;
    __shared__ float s_logit[20];

    const int tid  = threadIdx.x;
    const int wid  = tid >> 5;
    const int lane = tid & 31;

    // stage small tables once per block
    for (int i = tid; i < 512; i += 640) s_ws[i >> 6][i & 63] = ws[i];
    if (tid < 64) {
        s_fb[tid] = fb[tid];
        s_ow[tid] = out_w[tid];
        s_ob[tid] = out_b[tid];
    }

    const long long e = (long long)blockIdx.x * 20 + wid;   // this warp's edge
    const int4 ra = reinterpret_cast<const int4*>(edges)[e * 2];
    const int4 rb = reinterpret_cast<const int4*>(edges)[e * 2 + 1];
    const int eg = ra.x, vi = ra.y, vj = ra.z, rel = ra.w;
    const int e2vi = rb.z, e2vj = rb.w;

    if (wid == 0) {
        // vi / eg constant across segment: stage hu[vi] and attention once
        float2 h = *reinterpret_cast<const float2*>(&g_hu[(long long)vi * 64 + 2 * lane]);
        *reinterpret_cast<float2*>(&s_hu[2 * lane]) = h;
        if (lane == 0) s_att = natt[(long long)eg * n_nodes + vi];
    }
    __syncthreads();

    const int d = 2 * lane;
    const float2 f0 = *reinterpret_cast<const float2*>(&g_hc[(long long)e2vi * 64 + d]);
    const float2 f1 = *reinterpret_cast<const float2*>(&s_hu[d]);
    const float2 f2 = *reinterpret_cast<const float2*>(&rel_table[(long long)rel * 64 + d]);
    const float2 f3 = *reinterpret_cast<const float2*>(&g_hc[(long long)e2vj * 64 + d]);
    const float2 f4 = *reinterpret_cast<const float2*>(&g_hu[(long long)vj * 64 + d]);

    const float2 w0 = *reinterpret_cast<const float2*>(&s_ws[0][d]);
    const float2 w1 = *reinterpret_cast<const float2*>(&s_ws[1][d]);
    const float2 w2 = *reinterpret_cast<const float2*>(&s_ws[2][d]);
    const float2 w3 = *reinterpret_cast<const float2*>(&s_ws[3][d]);
    const float2 w4 = *reinterpret_cast<const float2*>(&s_ws[4][d]);
    const float2 w5 = *reinterpret_cast<const float2*>(&s_ws[5][d]);
    const float2 w6 = *reinterpret_cast<const float2*>(&s_ws[6][d]);
    const float2 w7 = *reinterpret_cast<const float2*>(&s_ws[7][d]);
    const float2 vb = *reinterpret_cast<const float2*>(&s_fb[d]);
    const float2 ow = *reinterpret_cast<const float2*>(&s_ow[d]);
    const float2 ob = *reinterpret_cast<const float2*>(&s_ob[d]);

    // factored interaction:
    // c3 = f0*w0 + (f0*f2)*w1 + f1*w4 + (f1*f2)*w5   (coefficient of f3)
    // c4 = f0*w2 + (f0*f2)*w3 + f1*w6 + (f1*f2)*w7   (coefficient of f4)
    float lsum;
    {
        float a1x = f0.x * f2.x, a1y = f0.y * f2.y;
        float a3x = f1.x * f2.x, a3y = f1.y * f2.y;
        float c3x = fmaf(f0.x, w0.x, fmaf(a1x, w1.x, fmaf(f1.x, w4.x, a3x * w5.x)));
        float c3y = fmaf(f0.y, w0.y, fmaf(a1y, w1.y, fmaf(f1.y, w4.y, a3y * w5.y)));
        float c4x = fmaf(f0.x, w2.x, fmaf(a1x, w3.x, fmaf(f1.x, w6.x, a3x * w7.x)));
        float c4y = fmaf(f0.y, w2.y, fmaf(a1y, w3.y, fmaf(f1.y, w6.y, a3y * w7.y)));
        float oxv = fmaf(f3.x, c3x, fmaf(f4.x, c4x, vb.x));
        float oyv = fmaf(f3.y, c3y, fmaf(f4.y, c4y, vb.y));
        float px = fmaf(fmaxf(oxv, 0.0f), ow.x, ob.x);
        float py = fmaf(fmaxf(oyv, 0.0f), ow.y, ob.y);
        lsum = px + py;
    }
#pragma unroll
    for (int s = 16; s > 0; s >>= 1) lsum += __shfl_xor_sync(0xFFFFFFFFu, lsum, s);
    // lsum now holds this edge's logit in every lane
    if (lane == 0) s_logit[wid] = lsum;
    __syncthreads();

    // every warp redundantly computes segment max / denom (no extra barrier)
    float l = (lane < 20) ? s_logit[lane] : -1e30f;
    float m = l;
#pragma unroll
    for (int s = 16; s > 0; s >>= 1) m = fmaxf(m, __shfl_xor_sync(0xFFFFFFFFu, m, s));
    float ev = (lane < 20) ? __expf(l - m) : 0.0f;
#pragma unroll
    for (int s = 16; s > 0; s >>= 1) ev += __shfl_xor_sync(0xFFFFFFFFu, ev, s);

    if (lane == 0) {
        float trans = __expf(lsum - m) / ev;
        float contrib = trans * s_att * edges_y[e];
        atomicAdd(&out[(long long)eg * n_nodes + vj], contrib);
    }
}

// ---------------------------------------------------------------------------
extern "C" void kernel_launch(void* const* d_in, const int* in_sizes, int n_in,
                              void* d_out, int out_size)
{
    const float* natt    = (const float*)d_in[0];
    const int*   edges   = (const int*)d_in[1];
    const float* edges_y = (const float*)d_in[2];
    const float* hu_in   = (const float*)d_in[3];   // [1, n_nodes, 256]
    const float* hc_in   = (const float*)d_in[4];   // [n_mem, 64]
    const float* Wc      = (const float*)d_in[5];
    const float* bc      = (const float*)d_in[6];
    const float* Wu      = (const float*)d_in[7];
    const float* bu      = (const float*)d_in[8];
    const float* rel_t   = (const float*)d_in[9];
    const float* ws      = (const float*)d_in[10];
    const float* fb      = (const float*)d_in[11];
    const float* ow      = (const float*)d_in[12];
    const float* ob      = (const float*)d_in[13];

    const int E       = in_sizes[2];
    const int n_nodes = in_sizes[3] / 256;
    const int n_mem   = in_sizes[4] / 64;
    const int n_seg   = E / 20;

    float* hc; cudaGetSymbolAddress((void**)&hc, g_hc);
    float* hu; cudaGetSymbolAddress((void**)&hu, g_hu);

    cudaMemsetAsync(d_out, 0, (size_t)out_size * sizeof(float));

    proj_tanh_kernel<64><<<(n_mem + 255) / 256, 256>>>(hc_in, Wc, bc, hc, n_mem);
    proj_tanh_kernel<256><<<(n_nodes + 255) / 256, 256>>>(hu_in, Wu, bu, hu, n_nodes);

    edge_kernel<<<n_seg, 640>>>(natt, edges, edges_y, rel_t, ws, fb, ow, ob,
                                (float*)d_out, n_nodes);
}

// round 2
// speedup vs baseline: 1.2648x; 1.2648x over previous
#include <cuda_runtime.h>

// ---------------------------------------------------------------------------
// Problem constants (fixed by the dataset): B=4, E=400000, N_NODES=50000,
// N_REL=500, D=64, D_LG=256, K_PER_VI=20, N_MEM=131072.
// Scratch for projected tables (device globals: no allocation allowed).
// ---------------------------------------------------------------------------
__device__ float g_hc[131072 * 64];   // tanh(hidden_con @ Wc + bc)
__device__ float g_hu[50000 * 64];    // tanh(hidden_uncon @ Wu + bu)

// ---------------- packed f32x2 helpers (sm_103a) ----------------
__device__ __forceinline__ void unpack2(unsigned long long u, float& x, float& y) {
    asm("mov.b64 {%0,%1}, %2;" : "=f"(x), "=f"(y) : "l"(u));
}
__device__ __forceinline__ void fma2(unsigned long long& d,
                                     unsigned long long a, unsigned long long b) {
    asm("fma.rn.f32x2 %0, %1, %2, %0;" : "+l"(d) : "l"(a), "l"(b));
}

__device__ __forceinline__ float tanh_fast(float x) {
    float e = __expf(-2.0f * fabsf(x));
    float t = (1.0f - e) / (1.0f + e);
    return copysignf(t, x);
}

// ---------------------------------------------------------------------------
// Projection: out[row, 0:64] = tanh(X[row, 0:K] @ W[K,64] + bias)
// 256 threads = 8 warps; each warp computes 8 rows x 64 cols (2 cols/lane).
// X is staged into smem DUPLICATED (x,x) so one broadcast LDS.64 feeds the
// f32x2 FMA directly (no mov.b64 packing in the hot loop). W rows are read
// via __ldg (table is L1-resident, 256B/warp conflict-free).
// ---------------------------------------------------------------------------
template <int K>
__global__ void __launch_bounds__(256) proj_tanh_kernel(
    const float* __restrict__ X, const float* __restrict__ W,
    const float* __restrict__ bias, float* __restrict__ out, int rows)
{
    __shared__ __align__(16) float Xs2[64][128];   // 32 KB: x duplicated pairs

    const int tid  = threadIdx.x;
    const int warp = tid >> 5;
    const int lane = tid & 31;
    const int r0   = blockIdx.x * 64;
    const int rb   = warp * 8;                     // this warp's row base in tile

    unsigned long long acc[8];
#pragma unroll
    for (int r = 0; r < 8; r++) acc[r] = 0ull;

    for (int k0 = 0; k0 < K; k0 += 64) {
        // stage X tile rows r0..r0+63, cols k0..k0+63, duplicated.
        // consecutive tids read consecutive floats of a row (coalesced),
        // write float2(x,x) -> conflict-free STS.64.
#pragma unroll
        for (int i = 0; i < 16; i++) {
            int idx = tid + i * 256;               // 0..4095
            int r = idx >> 6, c = idx & 63;
            int row = r0 + r;
            float x = (row < rows) ? __ldg(&X[(size_t)row * K + k0 + c]) : 0.0f;
            *reinterpret_cast<float2*>(&Xs2[r][2 * c]) = make_float2(x, x);
        }
        __syncthreads();

        const float* Wk = W + (size_t)k0 * 64 + 2 * lane;
#pragma unroll 8
        for (int kk = 0; kk < 64; kk++) {
            unsigned long long wv =
                *reinterpret_cast<const unsigned long long*>(&Wk[(size_t)kk * 64]);
#pragma unroll
            for (int r = 0; r < 8; r++) {
                unsigned long long xv =
                    *reinterpret_cast<const unsigned long long*>(&Xs2[rb + r][2 * kk]);
                fma2(acc[r], xv, wv);
            }
        }
        __syncthreads();
    }

    // epilogue: bias + tanh + coalesced float2 stores
    const float bx = bias[2 * lane];
    const float by = bias[2 * lane + 1];
#pragma unroll
    for (int r = 0; r < 8; r++) {
        int row = r0 + rb + r;
        if (row < rows) {
            float a, b;
            unpack2(acc[r], a, b);
            *reinterpret_cast<float2*>(&out[(size_t)row * 64 + 2 * lane]) =
                make_float2(tanh_fast(a + bx), tanh_fast(b + by));
        }
    }
}

// ---------------------------------------------------------------------------
// Edge kernel: one block per vi-segment (exactly 20 contiguous edges, vi/eg
// constant within segment). One warp per edge; lane handles dims (2l, 2l+1).
// Computes F-layer logits, segment softmax, and scatters transition*att*y
// directly to out[eg, vj] via atomicAdd (vj-segment sum collapses to this).
// ---------------------------------------------------------------------------
__global__ void __launch_bounds__(640) edge_kernel(
    const float* __restrict__ natt, const int* __restrict__ edges,
    const float* __restrict__ edges_y, const float* __restrict__ rel_table,
    const float* __restrict__ ws, const float* __restrict__ fb,
    const float* __restrict__ out_w, const float* __restrict__ out_b,
    float* __restrict__ out, int n_nodes)
{
    __shared__ __align__(16) float s_ws[8][64];
    __shared__ __align__(16) float s_fb[64];
    __shared__ __align__(16) float s_ow[64];
    __shared__ __align__(16) float s_ob[64];
    __shared__ __align__(16) float s_hu[64];
    __shared__ float s_att;
    __shared__ float s_logit[20];

    const int tid  = threadIdx.x;
    const int wid  = tid >> 5;
    const int lane = tid & 31;

    // stage small tables once per block
    for (int i = tid; i < 512; i += 640) s_ws[i >> 6][i & 63] = ws[i];
    if (tid < 64) {
        s_fb[tid] = fb[tid];
        s_ow[tid] = out_w[tid];
        s_ob[tid] = out_b[tid];
    }

    const long long e = (long long)blockIdx.x * 20 + wid;   // this warp's edge
    const int4 ra = reinterpret_cast<const int4*>(edges)[e * 2];
    const int4 rb = reinterpret_cast<const int4*>(edges)[e * 2 + 1];
    const int eg = ra.x, vi = ra.y, vj = ra.z, rel = ra.w;
    const int e2vi = rb.z, e2vj = rb.w;
    const float ey = (lane == 0) ? edges_y[e] : 0.0f;

    if (wid == 0) {
        // vi / eg constant across segment: stage hu[vi] and attention once
        float2 h = *reinterpret_cast<const float2*>(&g_hu[(long long)vi * 64 + 2 * lane]);
        *reinterpret_cast<float2*>(&s_hu[2 * lane]) = h;
        if (lane == 0) s_att = natt[(long long)eg * n_nodes + vi];
    }
    __syncthreads();

    const int d = 2 * lane;
    const float2 f0 = *reinterpret_cast<const float2*>(&g_hc[(long long)e2vi * 64 + d]);
    const float2 f1 = *reinterpret_cast<const float2*>(&s_hu[d]);
    const float2 f2 = *reinterpret_cast<const float2*>(&rel_table[(long long)rel * 64 + d]);
    const float2 f3 = *reinterpret_cast<const float2*>(&g_hc[(long long)e2vj * 64 + d]);
    const float2 f4 = *reinterpret_cast<const float2*>(&g_hu[(long long)vj * 64 + d]);

    const float2 w0 = *reinterpret_cast<const float2*>(&s_ws[0][d]);
    const float2 w1 = *reinterpret_cast<const float2*>(&s_ws[1][d]);
    const float2 w2 = *reinterpret_cast<const float2*>(&s_ws[2][d]);
    const float2 w3 = *reinterpret_cast<const float2*>(&s_ws[3][d]);
    const float2 w4 = *reinterpret_cast<const float2*>(&s_ws[4][d]);
    const float2 w5 = *reinterpret_cast<const float2*>(&s_ws[5][d]);
    const float2 w6 = *reinterpret_cast<const float2*>(&s_ws[6][d]);
    const float2 w7 = *reinterpret_cast<const float2*>(&s_ws[7][d]);
    const float2 vb = *reinterpret_cast<const float2*>(&s_fb[d]);
    const float2 ow = *reinterpret_cast<const float2*>(&s_ow[d]);
    const float2 ob = *reinterpret_cast<const float2*>(&s_ob[d]);

    // factored interaction:
    // c3 = f0*w0 + (f0*f2)*w1 + f1*w4 + (f1*f2)*w5   (coefficient of f3)
    // c4 = f0*w2 + (f0*f2)*w3 + f1*w6 + (f1*f2)*w7   (coefficient of f4)
    float lsum;
    {
        float a1x = f0.x * f2.x, a1y = f0.y * f2.y;
        float a3x = f1.x * f2.x, a3y = f1.y * f2.y;
        float c3x = fmaf(f0.x, w0.x, fmaf(a1x, w1.x, fmaf(f1.x, w4.x, a3x * w5.x)));
        float c3y = fmaf(f0.y, w0.y, fmaf(a1y, w1.y, fmaf(f1.y, w4.y, a3y * w5.y)));
        float c4x = fmaf(f0.x, w2.x, fmaf(a1x, w3.x, fmaf(f1.x, w6.x, a3x * w7.x)));
        float c4y = fmaf(f0.y, w2.y, fmaf(a1y, w3.y, fmaf(f1.y, w6.y, a3y * w7.y)));
        float oxv = fmaf(f3.x, c3x, fmaf(f4.x, c4x, vb.x));
        float oyv = fmaf(f3.y, c3y, fmaf(f4.y, c4y, vb.y));
        float px = fmaf(fmaxf(oxv, 0.0f), ow.x, ob.x);
        float py = fmaf(fmaxf(oyv, 0.0f), ow.y, ob.y);
        lsum = px + py;
    }
#pragma unroll
    for (int s = 16; s > 0; s >>= 1) lsum += __shfl_xor_sync(0xFFFFFFFFu, lsum, s);
    // lsum now holds this edge's logit in every lane
    if (lane == 0) s_logit[wid] = lsum;
    __syncthreads();

    // every warp redundantly computes segment max / denom (no extra barrier)
    float l = (lane < 20) ? s_logit[lane] : -1e30f;
    float m = l;
#pragma unroll
    for (int s = 16; s > 0; s >>= 1) m = fmaxf(m, __shfl_xor_sync(0xFFFFFFFFu, m, s));
    float ev = (lane < 20) ? __expf(l - m) : 0.0f;
#pragma unroll
    for (int s = 16; s > 0; s >>= 1) ev += __shfl_xor_sync(0xFFFFFFFFu, ev, s);

    if (lane == 0) {
        float trans = __expf(lsum - m) / ev;
        float contrib = trans * s_att * ey;
        atomicAdd(&out[(long long)eg * n_nodes + vj], contrib);
    }
}

// ---------------------------------------------------------------------------
extern "C" void kernel_launch(void* const* d_in, const int* in_sizes, int n_in,
                              void* d_out, int out_size)
{
    const float* natt    = (const float*)d_in[0];
    const int*   edges   = (const int*)d_in[1];
    const float* edges_y = (const float*)d_in[2];
    const float* hu_in   = (const float*)d_in[3];   // [1, n_nodes, 256]
    const float* hc_in   = (const float*)d_in[4];   // [n_mem, 64]
    const float* Wc      = (const float*)d_in[5];
    const float* bc      = (const float*)d_in[6];
    const float* Wu      = (const float*)d_in[7];
    const float* bu      = (const float*)d_in[8];
    const float* rel_t   = (const float*)d_in[9];
    const float* ws      = (const float*)d_in[10];
    const float* fb      = (const float*)d_in[11];
    const float* ow      = (const float*)d_in[12];
    const float* ob      = (const float*)d_in[13];

    const int E       = in_sizes[2];
    const int n_nodes = in_sizes[3] / 256;
    const int n_mem   = in_sizes[4] / 64;
    const int n_seg   = E / 20;

    float* hc; cudaGetSymbolAddress((void**)&hc, g_hc);
    float* hu; cudaGetSymbolAddress((void**)&hu, g_hu);

    cudaMemsetAsync(d_out, 0, (size_t)out_size * sizeof(float));

    proj_tanh_kernel<64><<<(n_mem + 63) / 64, 256>>>(hc_in, Wc, bc, hc, n_mem);
    proj_tanh_kernel<256><<<(n_nodes + 63) / 64, 256>>>(hu_in, Wu, bu, hu, n_nodes);

    edge_kernel<<<n_seg, 640>>>(natt, edges, edges_y, rel_t, ws, fb, ow, ob,
                                (float*)d_out, n_nodes);
}

// round 3
// speedup vs baseline: 1.3647x; 1.0790x over previous
#include <cuda_runtime.h>

// ---------------------------------------------------------------------------
// Problem constants (fixed by the dataset): B=4, E=400000, N_NODES=50000,
// N_REL=500, D=64, D_LG=256, K_PER_VI=20, N_MEM=131072.
// Scratch for projected tables (device globals: no allocation allowed).
// ---------------------------------------------------------------------------
__device__ float g_hc[131072 * 64];   // tanh(hidden_con @ Wc + bc)
__device__ float g_hu[50000 * 64];    // tanh(hidden_uncon @ Wu + bu)

// ---------------- packed f32x2 helpers (sm_103a) ----------------
__device__ __forceinline__ void unpack2(unsigned long long u, float& x, float& y) {
    asm("mov.b64 {%0,%1}, %2;" : "=f"(x), "=f"(y) : "l"(u));
}
__device__ __forceinline__ void fma2(unsigned long long& d,
                                     unsigned long long a, unsigned long long b) {
    asm("fma.rn.f32x2 %0, %1, %2, %0;" : "+l"(d) : "l"(a), "l"(b));
}

__device__ __forceinline__ float tanh_fast(float x) {
    float e = __expf(-2.0f * fabsf(x));
    float t = (1.0f - e) / (1.0f + e);
    return copysignf(t, x);
}

// ---------------------------------------------------------------------------
// Projection: out[row, 0:64] = tanh(X[row, 0:K] @ W[K,64] + bias)
//
// Register-tiled outer product (round-2 was smem-operand-bandwidth bound):
//   block = 256 rows x 64 cols, 256 threads = 8 warps
//   warp (rg, cg): rg = row-group of 128 rows, cg = col-group of 16 cols
//   thread tile = 4 rows x 16 cols; rows strided {l, l+32, l+64, l+96} so the
//   per-k x fetch is a contiguous 256B LDS.64 across the warp.
//   X staged transposed+duplicated: XsT[k][2r]=(x,x) feeds fma.rn.f32x2 directly.
//   Per warp-k: 4 LDS.64 (x) + 4 LDS.128 broadcast (w) + 32 FFMA2
//   -> FMA pipe 64 cyc/SMSP vs ~9 crossbar cyc: FMA-bound.
// Dynamic smem: XsT region 17408 floats (reused as [256][68] output stage),
// Ws 2048 floats => 77824 bytes, 2 blocks/SM.
// ---------------------------------------------------------------------------
template <int K>
__global__ void __launch_bounds__(256, 2) proj_tanh_kernel(
    const float* __restrict__ X, const float* __restrict__ W,
    const float* __restrict__ bias, float* __restrict__ out, int rows)
{
    extern __shared__ float sm[];
    float* XsT = sm;             // [32][514] x-pairs; later reused as [256][68]
    float* Ws  = sm + 17408;     // [32][64]

    const int tid  = threadIdx.x;
    const int lane = tid & 31;
    const int warp = tid >> 5;
    const int rg   = warp >> 2;          // 0..1  (128 rows each)
    const int cg   = warp & 3;           // 0..3  (16 cols each)
    const int r0   = blockIdx.x * 256;

    unsigned long long acc[4][8];
#pragma unroll
    for (int r = 0; r < 4; r++)
#pragma unroll
        for (int j = 0; j < 8; j++) acc[r][j] = 0ull;

    for (int k0 = 0; k0 < K; k0 += 32) {
        __syncthreads();   // protect XsT/Ws reuse from previous chunk's readers

        // ---- stage X chunk: 256 rows x 32 k, transposed + duplicated ----
#pragma unroll
        for (int i = 0; i < 8; i++) {
            int idx = tid + i * 256;          // 0..2047 float4s
            int k4  = idx & 7;                // k quad
            int r   = idx >> 3;               // row 0..255
            int row = r0 + r;
            float4 v = make_float4(0.f, 0.f, 0.f, 0.f);
            if (row < rows)
                v = *reinterpret_cast<const float4*>(&X[(size_t)row * K + k0 + 4 * k4]);
            float* p = &XsT[(4 * k4) * 514 + 2 * r];
            *reinterpret_cast<float2*>(p)        = make_float2(v.x, v.x);
            *reinterpret_cast<float2*>(p + 514)  = make_float2(v.y, v.y);
            *reinterpret_cast<float2*>(p + 1028) = make_float2(v.z, v.z);
            *reinterpret_cast<float2*>(p + 1542) = make_float2(v.w, v.w);
        }
        // ---- stage W chunk: 32 x 64 ----
#pragma unroll
        for (int i = 0; i < 2; i++) {
            int idx = tid + i * 256;          // 0..511 float4s
            *reinterpret_cast<float4*>(&Ws[4 * idx]) =
                *reinterpret_cast<const float4*>(&W[(size_t)k0 * 64 + 4 * idx]);
        }
        __syncthreads();

        // ---- compute ----
        const float* xb = &XsT[2 * (rg * 128 + lane)];
        const float* wb = &Ws[cg * 16];
#pragma unroll 4
        for (int kk = 0; kk < 32; kk++) {
            const ulonglong2* wp = reinterpret_cast<const ulonglong2*>(wb + (size_t)kk * 64);
            ulonglong2 wa = wp[0], wb2 = wp[1], wc = wp[2], wd = wp[3];
            unsigned long long wv[8] = {wa.x, wa.y, wb2.x, wb2.y, wc.x, wc.y, wd.x, wd.y};
            const unsigned long long* xp =
                reinterpret_cast<const unsigned long long*>(xb + (size_t)kk * 514);
            unsigned long long xv[4] = {xp[0], xp[32], xp[64], xp[96]};
#pragma unroll
            for (int r = 0; r < 4; r++)
#pragma unroll
                for (int j = 0; j < 8; j++) fma2(acc[r][j], xv[r], wv[j]);
        }
    }

    // ---- epilogue: bias + tanh, stage to smem, coalesced float4 writeback ----
    __syncthreads();
    float bv[16];
#pragma unroll
    for (int j = 0; j < 16; j++) bv[j] = __ldg(&bias[cg * 16 + j]);
#pragma unroll
    for (int r = 0; r < 4; r++) {
        int rin = rg * 128 + 32 * r + lane;
        float* dst = &XsT[rin * 68 + cg * 16];
#pragma unroll
        for (int j = 0; j < 8; j++) {
            float a, b;
            unpack2(acc[r][j], a, b);
            *reinterpret_cast<float2*>(dst + 2 * j) =
                make_float2(tanh_fast(a + bv[2 * j]), tanh_fast(b + bv[2 * j + 1]));
        }
    }
    __syncthreads();
#pragma unroll
    for (int i = 0; i < 16; i++) {
        int idx = tid + i * 256;              // 0..4095 float4s
        int r = idx >> 4, c4 = idx & 15;
        int row = r0 + r;
        if (row < rows)
            *reinterpret_cast<float4*>(&out[(size_t)row * 64 + 4 * c4]) =
                *reinterpret_cast<const float4*>(&XsT[r * 68 + 4 * c4]);
    }
}

// ---------------------------------------------------------------------------
// Edge kernel: one block per vi-segment (exactly 20 contiguous edges, vi/eg
// constant within segment). One warp per edge; lane handles dims (2l, 2l+1).
// Computes F-layer logits, segment softmax, and scatters transition*att*y
// directly to out[eg, vj] via atomicAdd (vj-segment sum collapses to this).
// ---------------------------------------------------------------------------
__global__ void __launch_bounds__(640) edge_kernel(
    const float* __restrict__ natt, const int* __restrict__ edges,
    const float* __restrict__ edges_y, const float* __restrict__ rel_table,
    const float* __restrict__ ws, const float* __restrict__ fb,
    const float* __restrict__ out_w, const float* __restrict__ out_b,
    float* __restrict__ out, int n_nodes)
{
    __shared__ __align__(16) float s_ws[8][64];
    __shared__ __align__(16) float s_fb[64];
    __shared__ __align__(16) float s_ow[64];
    __shared__ __align__(16) float s_ob[64];
    __shared__ __align__(16) float s_hu[64];
    __shared__ float s_att;
    __shared__ float s_logit[20];

    const int tid  = threadIdx.x;
    const int wid  = tid >> 5;
    const int lane = tid & 31;

    // stage small tables once per block
    for (int i = tid; i < 512; i += 640) s_ws[i >> 6][i & 63] = ws[i];
    if (tid < 64) {
        s_fb[tid] = fb[tid];
        s_ow[tid] = out_w[tid];
        s_ob[tid] = out_b[tid];
    }

    const long long e = (long long)blockIdx.x * 20 + wid;   // this warp's edge
    const int4 ra = reinterpret_cast<const int4*>(edges)[e * 2];
    const int4 rb = reinterpret_cast<const int4*>(edges)[e * 2 + 1];
    const int eg = ra.x, vi = ra.y, vj = ra.z, rel = ra.w;
    const int e2vi = rb.z, e2vj = rb.w;
    const float ey = (lane == 0) ? edges_y[e] : 0.0f;

    if (wid == 0) {
        // vi / eg constant across segment: stage hu[vi] and attention once
        float2 h = *reinterpret_cast<const float2*>(&g_hu[(long long)vi * 64 + 2 * lane]);
        *reinterpret_cast<float2*>(&s_hu[2 * lane]) = h;
        if (lane == 0) s_att = natt[(long long)eg * n_nodes + vi];
    }
    __syncthreads();

    const int d = 2 * lane;
    const float2 f0 = *reinterpret_cast<const float2*>(&g_hc[(long long)e2vi * 64 + d]);
    const float2 f1 = *reinterpret_cast<const float2*>(&s_hu[d]);
    const float2 f2 = *reinterpret_cast<const float2*>(&rel_table[(long long)rel * 64 + d]);
    const float2 f3 = *reinterpret_cast<const float2*>(&g_hc[(long long)e2vj * 64 + d]);
    const float2 f4 = *reinterpret_cast<const float2*>(&g_hu[(long long)vj * 64 + d]);

    const float2 w0 = *reinterpret_cast<const float2*>(&s_ws[0][d]);
    const float2 w1 = *reinterpret_cast<const float2*>(&s_ws[1][d]);
    const float2 w2 = *reinterpret_cast<const float2*>(&s_ws[2][d]);
    const float2 w3 = *reinterpret_cast<const float2*>(&s_ws[3][d]);
    const float2 w4 = *reinterpret_cast<const float2*>(&s_ws[4][d]);
    const float2 w5 = *reinterpret_cast<const float2*>(&s_ws[5][d]);
    const float2 w6 = *reinterpret_cast<const float2*>(&s_ws[6][d]);
    const float2 w7 = *reinterpret_cast<const float2*>(&s_ws[7][d]);
    const float2 vb = *reinterpret_cast<const float2*>(&s_fb[d]);
    const float2 ow = *reinterpret_cast<const float2*>(&s_ow[d]);
    const float2 ob = *reinterpret_cast<const float2*>(&s_ob[d]);

    // factored interaction:
    // c3 = f0*w0 + (f0*f2)*w1 + f1*w4 + (f1*f2)*w5   (coefficient of f3)
    // c4 = f0*w2 + (f0*f2)*w3 + f1*w6 + (f1*f2)*w7   (coefficient of f4)
    float lsum;
    {
        float a1x = f0.x * f2.x, a1y = f0.y * f2.y;
        float a3x = f1.x * f2.x, a3y = f1.y * f2.y;
        float c3x = fmaf(f0.x, w0.x, fmaf(a1x, w1.x, fmaf(f1.x, w4.x, a3x * w5.x)));
        float c3y = fmaf(f0.y, w0.y, fmaf(a1y, w1.y, fmaf(f1.y, w4.y, a3y * w5.y)));
        float c4x = fmaf(f0.x, w2.x, fmaf(a1x, w3.x, fmaf(f1.x, w6.x, a3x * w7.x)));
        float c4y = fmaf(f0.y, w2.y, fmaf(a1y, w3.y, fmaf(f1.y, w6.y, a3y * w7.y)));
        float oxv = fmaf(f3.x, c3x, fmaf(f4.x, c4x, vb.x));
        float oyv = fmaf(f3.y, c3y, fmaf(f4.y, c4y, vb.y));
        float px = fmaf(fmaxf(oxv, 0.0f), ow.x, ob.x);
        float py = fmaf(fmaxf(oyv, 0.0f), ow.y, ob.y);
        lsum = px + py;
    }
#pragma unroll
    for (int s = 16; s > 0; s >>= 1) lsum += __shfl_xor_sync(0xFFFFFFFFu, lsum, s);
    // lsum now holds this edge's logit in every lane
    if (lane == 0) s_logit[wid] = lsum;
    __syncthreads();

    // every warp redundantly computes segment max / denom (no extra barrier)
    float l = (lane < 20) ? s_logit[lane] : -1e30f;
    float m = l;
#pragma unroll
    for (int s = 16; s > 0; s >>= 1) m = fmaxf(m, __shfl_xor_sync(0xFFFFFFFFu, m, s));
    float ev = (lane < 20) ? __expf(l - m) : 0.0f;
#pragma unroll
    for (int s = 16; s > 0; s >>= 1) ev += __shfl_xor_sync(0xFFFFFFFFu, ev, s);

    if (lane == 0) {
        float trans = __expf(lsum - m) / ev;
        float contrib = trans * s_att * ey;
        atomicAdd(&out[(long long)eg * n_nodes + vj], contrib);
    }
}

// ---------------------------------------------------------------------------
extern "C" void kernel_launch(void* const* d_in, const int* in_sizes, int n_in,
                              void* d_out, int out_size)
{
    const float* natt    = (const float*)d_in[0];
    const int*   edges   = (const int*)d_in[1];
    const float* edges_y = (const float*)d_in[2];
    const float* hu_in   = (const float*)d_in[3];   // [1, n_nodes, 256]
    const float* hc_in   = (const float*)d_in[4];   // [n_mem, 64]
    const float* Wc      = (const float*)d_in[5];
    const float* bc      = (const float*)d_in[6];
    const float* Wu      = (const float*)d_in[7];
    const float* bu      = (const float*)d_in[8];
    const float* rel_t   = (const float*)d_in[9];
    const float* ws      = (const float*)d_in[10];
    const float* fb      = (const float*)d_in[11];
    const float* ow      = (const float*)d_in[12];
    const float* ob      = (const float*)d_in[13];

    const int E       = in_sizes[2];
    const int n_nodes = in_sizes[3] / 256;
    const int n_mem   = in_sizes[4] / 64;
    const int n_seg   = E / 20;

    float* hc; cudaGetSymbolAddress((void**)&hc, g_hc);
    float* hu; cudaGetSymbolAddress((void**)&hu, g_hu);

    const int dyn_smem = (17408 + 2048) * 4;   // 77824 bytes
    cudaFuncSetAttribute(proj_tanh_kernel<64>,
                         cudaFuncAttributeMaxDynamicSharedMemorySize, dyn_smem);
    cudaFuncSetAttribute(proj_tanh_kernel<256>,
                         cudaFuncAttributeMaxDynamicSharedMemorySize, dyn_smem);

    cudaMemsetAsync(d_out, 0, (size_t)out_size * sizeof(float));

    proj_tanh_kernel<64><<<(n_mem + 255) / 256, 256, dyn_smem>>>(hc_in, Wc, bc, hc, n_mem);
    proj_tanh_kernel<256><<<(n_nodes + 255) / 256, 256, dyn_smem>>>(hu_in, Wu, bu, hu, n_nodes);

    edge_kernel<<<n_seg, 640>>>(natt, edges, edges_y, rel_t, ws, fb, ow, ob,
                                (float*)d_out, n_nodes);
}

// round 4
// speedup vs baseline: 1.6314x; 1.1954x over previous
#include <cuda_runtime.h>

// ---------------------------------------------------------------------------
// Problem constants: B=4, E=400000, N_NODES=50000, N_REL=500, D=64, D_LG=256,
// K_PER_VI=20, N_MEM=131072. Scratch via device globals (no allocation).
// ---------------------------------------------------------------------------
__device__ float g_hc[131072 * 64];   // tanh(hidden_con @ Wc + bc)
__device__ float g_hu[50000 * 64];    // tanh(hidden_uncon @ Wu + bu)

// ---------------- packed f32x2 helpers (sm_103a) ----------------
__device__ __forceinline__ void unpack2(unsigned long long u, float& x, float& y) {
    asm("mov.b64 {%0,%1}, %2;" : "=f"(x), "=f"(y) : "l"(u));
}
__device__ __forceinline__ void fma2(unsigned long long& d,
                                     unsigned long long a, unsigned long long b) {
    asm("fma.rn.f32x2 %0, %1, %2, %0;" : "+l"(d) : "l"(a), "l"(b));
}

__device__ __forceinline__ float tanh_fast(float x) {
    float e = __expf(-2.0f * fabsf(x));
    float t = (1.0f - e) / (1.0f + e);
    return copysignf(t, x);
}

// ---------------------------------------------------------------------------
// Fused projection kernel: out[row,0:64] = tanh(X[row,0:K] @ W[K,64] + bias)
// for BOTH tables in one launch (block range split).
//
// Tile: block = 128 rows x 64 cols, 256 threads = 8 warps.
//   warp w owns rows [16w,16w+16); lane: rp=lane&7 -> row pair 2*rp(+1),
//   cg=lane>>3 -> 16-col group. Thread tile = 2 rows x 16 cols (16 u64 accs).
// X staged transposed + duplicated: XsT[k][2r]=(x,x); the per-kk x fetch is
// ONE LDS.128 giving (x0,x0,x1,x1) for both rows, 128B/warp conflict-free.
// W staged [32][64]; per-kk 4 LDS.128, 8-way broadcast.
// Per kk: 5 LDS + 16 FFMA2 -> crossbar 5 cyc per 8-cyc FMA window: FMA-bound.
// Regs ~75 -> 3 blocks/SM (24 warps) via __launch_bounds__(256,3).
// ---------------------------------------------------------------------------
__global__ void __launch_bounds__(256, 3) proj_both_kernel(
    const float* __restrict__ Xc, const float* __restrict__ Wc,
    const float* __restrict__ bc, int rows_c, int nb_c,
    const float* __restrict__ Xu, const float* __restrict__ Wu,
    const float* __restrict__ bu, int rows_u)
{
    extern __shared__ float sm[];
    float* XsT = sm;            // chunk [32][260]; epilogue reuse [128][68]
    float* Ws  = sm + 8704;     // [32][64]

    const float *X, *W, *bias;
    float* out;
    int rows, K, bid;
    if ((int)blockIdx.x < nb_c) {
        X = Xc; W = Wc; bias = bc; out = g_hc; rows = rows_c; K = 64;
        bid = blockIdx.x;
    } else {
        X = Xu; W = Wu; bias = bu; out = g_hu; rows = rows_u; K = 256;
        bid = blockIdx.x - nb_c;
    }

    const int tid  = threadIdx.x;
    const int lane = tid & 31;
    const int warp = tid >> 5;
    const int cg   = lane >> 3;             // 0..3: 16-col group
    const int rp   = lane & 7;              // row-pair index
    const int r0   = bid * 128;
    const int row_base = warp * 16 + 2 * rp;   // rows row_base, row_base+1

    unsigned long long acc[2][8];
#pragma unroll
    for (int r = 0; r < 2; r++)
#pragma unroll
        for (int j = 0; j < 8; j++) acc[r][j] = 0ull;

    for (int k0 = 0; k0 < K; k0 += 32) {
        __syncthreads();
        // ---- stage X chunk: 128 rows x 32 k, transposed + duplicated ----
#pragma unroll
        for (int i = 0; i < 4; i++) {
            int idx = tid + i * 256;        // 0..1023 float4s
            int row = idx >> 3, k4 = idx & 7;
            float4 v = make_float4(0.f, 0.f, 0.f, 0.f);
            if (r0 + row < rows)
                v = *reinterpret_cast<const float4*>(
                        &X[(size_t)(r0 + row) * K + k0 + 4 * k4]);
            float* p = &XsT[(4 * k4) * 260 + 2 * row];
            *reinterpret_cast<float2*>(p)       = make_float2(v.x, v.x);
            *reinterpret_cast<float2*>(p + 260) = make_float2(v.y, v.y);
            *reinterpret_cast<float2*>(p + 520) = make_float2(v.z, v.z);
            *reinterpret_cast<float2*>(p + 780) = make_float2(v.w, v.w);
        }
        // ---- stage W chunk: 32 x 64 ----
#pragma unroll
        for (int i = 0; i < 2; i++) {
            int idx = tid + i * 256;        // 0..511 float4s
            *reinterpret_cast<float4*>(&Ws[4 * idx]) =
                *reinterpret_cast<const float4*>(&W[(size_t)k0 * 64 + 4 * idx]);
        }
        __syncthreads();

        const float* xb = &XsT[2 * row_base];
        const float* wb = &Ws[cg * 16];
#pragma unroll 8
        for (int kk = 0; kk < 32; kk++) {
            ulonglong2 xq =
                *reinterpret_cast<const ulonglong2*>(xb + (size_t)kk * 260);
            const ulonglong2* wp =
                reinterpret_cast<const ulonglong2*>(wb + (size_t)kk * 64);
            ulonglong2 wA = wp[0], wB = wp[1], wC = wp[2], wD = wp[3];
            unsigned long long wv[8] = {wA.x, wA.y, wB.x, wB.y,
                                        wC.x, wC.y, wD.x, wD.y};
#pragma unroll
            for (int j = 0; j < 8; j++) fma2(acc[0][j], xq.x, wv[j]);
#pragma unroll
            for (int j = 0; j < 8; j++) fma2(acc[1][j], xq.y, wv[j]);
        }
    }

    // ---- epilogue: bias + tanh, stage to smem [128][68], coalesced stores --
    __syncthreads();
    float bv[16];
#pragma unroll
    for (int j = 0; j < 16; j++) bv[j] = __ldg(&bias[cg * 16 + j]);
#pragma unroll
    for (int r = 0; r < 2; r++) {
        float* dst = &XsT[(size_t)(row_base + r) * 68 + cg * 16];
#pragma unroll
        for (int j = 0; j < 8; j++) {
            float a, b;
            unpack2(acc[r][j], a, b);
            *reinterpret_cast<float2*>(dst + 2 * j) =
                make_float2(tanh_fast(a + bv[2 * j]), tanh_fast(b + bv[2 * j + 1]));
        }
    }
    __syncthreads();
#pragma unroll
    for (int i = 0; i < 8; i++) {
        int idx = tid + i * 256;            // 0..2047 float4s
        int row = idx >> 4, c4 = idx & 15;
        if (r0 + row < rows)
            *reinterpret_cast<float4*>(&out[(size_t)(r0 + row) * 64 + 4 * c4]) =
                *reinterpret_cast<const float4*>(&XsT[(size_t)row * 68 + 4 * c4]);
    }
}

// ---------------------------------------------------------------------------
// Edge kernel v2: 4 segments per block (640 thr = 20 warps), 5 warps/segment,
// 4 edges/warp. Each warp front-batches 16 independent float2 gathers (MLP 16)
// and amortizes weight loads over 4 edges. Segment softmax via smem logits +
// warp reduce; scatter by atomicAdd(out[eg, vj]).
// ---------------------------------------------------------------------------
__global__ void __launch_bounds__(640) edge_kernel(
    const float* __restrict__ natt, const int* __restrict__ edges,
    const float* __restrict__ edges_y, const float* __restrict__ rel_table,
    const float* __restrict__ ws, const float* __restrict__ fb,
    const float* __restrict__ out_w, const float* __restrict__ out_b,
    float* __restrict__ out, int n_nodes)
{
    __shared__ __align__(16) float s_ws[8][64];
    __shared__ __align__(16) float s_fb[64];
    __shared__ __align__(16) float s_ow[64];
    __shared__ __align__(16) float s_ob[64];
    __shared__ __align__(16) float s_hu[4][64];
    __shared__ float s_att[4];
    __shared__ float s_logit[4][20];

    const int tid   = threadIdx.x;
    const int wid   = tid >> 5;            // 0..19
    const int lane  = tid & 31;
    const int seg_l = wid / 5;             // 0..3 segment within block
    const int wis   = wid - seg_l * 5;     // 0..4 warp within segment

    // stage weights once per block
    for (int i = tid; i < 512; i += 640) s_ws[0][i] = ws[i];
    if (tid < 64) {
        s_fb[tid] = fb[tid];
        s_ow[tid] = out_w[tid];
        s_ob[tid] = out_b[tid];
    }

    const int seg    = blockIdx.x * 4 + seg_l;
    const long long e_base = (long long)seg * 20 + wis * 4;

    // lanes 0..7 load the 8 int4 of this warp's 4 edges (coalesced 128B)
    int4 a = make_int4(0, 0, 0, 0);
    if (lane < 8)
        a = __ldg(&reinterpret_cast<const int4*>(edges)[2 * e_base + lane]);

    // distribute per-edge fields (edge e: ra at lane 2e, rb at lane 2e+1)
    int vj0   = __shfl_sync(0xFFFFFFFFu, a.z, 0);
    int rel0  = __shfl_sync(0xFFFFFFFFu, a.w, 0);
    int e2vi0 = __shfl_sync(0xFFFFFFFFu, a.z, 1);
    int e2vj0 = __shfl_sync(0xFFFFFFFFu, a.w, 1);
    int vj1   = __shfl_sync(0xFFFFFFFFu, a.z, 2);
    int rel1  = __shfl_sync(0xFFFFFFFFu, a.w, 2);
    int e2vi1 = __shfl_sync(0xFFFFFFFFu, a.z, 3);
    int e2vj1 = __shfl_sync(0xFFFFFFFFu, a.w, 3);
    int vj2   = __shfl_sync(0xFFFFFFFFu, a.z, 4);
    int rel2  = __shfl_sync(0xFFFFFFFFu, a.w, 4);
    int e2vi2 = __shfl_sync(0xFFFFFFFFu, a.z, 5);
    int e2vj2 = __shfl_sync(0xFFFFFFFFu, a.w, 5);
    int vj3   = __shfl_sync(0xFFFFFFFFu, a.z, 6);
    int rel3  = __shfl_sync(0xFFFFFFFFu, a.w, 6);
    int e2vi3 = __shfl_sync(0xFFFFFFFFu, a.z, 7);
    int e2vj3 = __shfl_sync(0xFFFFFFFFu, a.w, 7);
    const int eg = __shfl_sync(0xFFFFFFFFu, a.x, 0);
    const int vi = __shfl_sync(0xFFFFFFFFu, a.y, 0);
    // vj for this lane's edge (lanes 0..3 use it at the end)
    const int vjL = __shfl_sync(0xFFFFFFFFu, a.z, 2 * (lane & 3));

    // stage hu[vi] + attention for this segment (first warp of segment)
    if (wis == 0) {
        float2 h = *reinterpret_cast<const float2*>(&g_hu[(size_t)vi * 64 + 2 * lane]);
        *reinterpret_cast<float2*>(&s_hu[seg_l][2 * lane]) = h;
        if (lane == 0) s_att[seg_l] = natt[(size_t)eg * n_nodes + vi];
    }

    // front-batched gathers: 16 independent float2 loads + edges_y
    const int d = 2 * lane;
    float2 f0a = *reinterpret_cast<const float2*>(&g_hc[(size_t)e2vi0 * 64 + d]);
    float2 f0b = *reinterpret_cast<const float2*>(&g_hc[(size_t)e2vi1 * 64 + d]);
    float2 f0c = *reinterpret_cast<const float2*>(&g_hc[(size_t)e2vi2 * 64 + d]);
    float2 f0d = *reinterpret_cast<const float2*>(&g_hc[(size_t)e2vi3 * 64 + d]);
    float2 f3a = *reinterpret_cast<const float2*>(&g_hc[(size_t)e2vj0 * 64 + d]);
    float2 f3b = *reinterpret_cast<const float2*>(&g_hc[(size_t)e2vj1 * 64 + d]);
    float2 f3c = *reinterpret_cast<const float2*>(&g_hc[(size_t)e2vj2 * 64 + d]);
    float2 f3d = *reinterpret_cast<const float2*>(&g_hc[(size_t)e2vj3 * 64 + d]);
    float2 f4a = *reinterpret_cast<const float2*>(&g_hu[(size_t)vj0 * 64 + d]);
    float2 f4b = *reinterpret_cast<const float2*>(&g_hu[(size_t)vj1 * 64 + d]);
    float2 f4c = *reinterpret_cast<const float2*>(&g_hu[(size_t)vj2 * 64 + d]);
    float2 f4d = *reinterpret_cast<const float2*>(&g_hu[(size_t)vj3 * 64 + d]);
    float2 f2a = *reinterpret_cast<const float2*>(&rel_table[(size_t)rel0 * 64 + d]);
    float2 f2b = *reinterpret_cast<const float2*>(&rel_table[(size_t)rel1 * 64 + d]);
    float2 f2c = *reinterpret_cast<const float2*>(&rel_table[(size_t)rel2 * 64 + d]);
    float2 f2d = *reinterpret_cast<const float2*>(&rel_table[(size_t)rel3 * 64 + d]);
    const float ey = (lane < 4) ? __ldg(&edges_y[e_base + lane]) : 0.0f;

    __syncthreads();   // s_hu / s_ws ready

    const float2 f1 = *reinterpret_cast<const float2*>(&s_hu[seg_l][d]);
    const float2 w0 = *reinterpret_cast<const float2*>(&s_ws[0][d]);
    const float2 w1 = *reinterpret_cast<const float2*>(&s_ws[1][d]);
    const float2 w2 = *reinterpret_cast<const float2*>(&s_ws[2][d]);
    const float2 w3 = *reinterpret_cast<const float2*>(&s_ws[3][d]);
    const float2 w4 = *reinterpret_cast<const float2*>(&s_ws[4][d]);
    const float2 w5 = *reinterpret_cast<const float2*>(&s_ws[5][d]);
    const float2 w6 = *reinterpret_cast<const float2*>(&s_ws[6][d]);
    const float2 w7 = *reinterpret_cast<const float2*>(&s_ws[7][d]);
    const float2 vb = *reinterpret_cast<const float2*>(&s_fb[d]);
    const float2 ow = *reinterpret_cast<const float2*>(&s_ow[d]);
    const float2 ob = *reinterpret_cast<const float2*>(&s_ob[d]);

    // f1-dependent terms shared by all 4 edges:
    //   c3 = f0*w0 + (f0*f2)*w1 + f1*w4 + (f1*f2)*w5   (coeff of f3)
    //   c4 = f0*w2 + (f0*f2)*w3 + f1*w6 + (f1*f2)*w7   (coeff of f4)
    const float h4x = f1.x * w4.x, h4y = f1.y * w4.y;
    const float h5x = f1.x * w5.x, h5y = f1.y * w5.y;
    const float h6x = f1.x * w6.x, h6y = f1.y * w6.y;
    const float h7x = f1.x * w7.x, h7y = f1.y * w7.y;

#define EDGE_LOGIT(f0v, f2v, f3v, f4v, lout)                                     \
    {                                                                            \
        float a1x = f0v.x * f2v.x, a1y = f0v.y * f2v.y;                          \
        float c3x = fmaf(f0v.x, w0.x, fmaf(a1x, w1.x, fmaf(f2v.x, h5x, h4x)));   \
        float c3y = fmaf(f0v.y, w0.y, fmaf(a1y, w1.y, fmaf(f2v.y, h5y, h4y)));   \
        float c4x = fmaf(f0v.x, w2.x, fmaf(a1x, w3.x, fmaf(f2v.x, h7x, h6x)));   \
        float c4y = fmaf(f0v.y, w2.y, fmaf(a1y, w3.y, fmaf(f2v.y, h7y, h6y)));   \
        float oxv = fmaf(f3v.x, c3x, fmaf(f4v.x, c4x, vb.x));                    \
        float oyv = fmaf(f3v.y, c3y, fmaf(f4v.y, c4y, vb.y));                    \
        float px  = fmaf(fmaxf(oxv, 0.0f), ow.x, ob.x);                          \
        float py  = fmaf(fmaxf(oyv, 0.0f), ow.y, ob.y);                          \
        lout = px + py;                                                          \
    }

    float l0, l1, l2, l3;
    EDGE_LOGIT(f0a, f2a, f3a, f4a, l0)
    EDGE_LOGIT(f0b, f2b, f3b, f4b, l1)
    EDGE_LOGIT(f0c, f2c, f3c, f4c, l2)
    EDGE_LOGIT(f0d, f2d, f3d, f4d, l3)
#undef EDGE_LOGIT

#pragma unroll
    for (int s = 16; s > 0; s >>= 1) {
        l0 += __shfl_xor_sync(0xFFFFFFFFu, l0, s);
        l1 += __shfl_xor_sync(0xFFFFFFFFu, l1, s);
        l2 += __shfl_xor_sync(0xFFFFFFFFu, l2, s);
        l3 += __shfl_xor_sync(0xFFFFFFFFu, l3, s);
    }
    if (lane == 0) {
        s_logit[seg_l][wis * 4 + 0] = l0;
        s_logit[seg_l][wis * 4 + 1] = l1;
        s_logit[seg_l][wis * 4 + 2] = l2;
        s_logit[seg_l][wis * 4 + 3] = l3;
    }
    __syncthreads();

    // segment softmax (each warp redundantly for its own segment)
    float l = (lane < 20) ? s_logit[seg_l][lane] : -1e30f;
    float m = l;
#pragma unroll
    for (int s = 16; s > 0; s >>= 1) m = fmaxf(m, __shfl_xor_sync(0xFFFFFFFFu, m, s));
    float ev = (lane < 20) ? __expf(l - m) : 0.0f;
#pragma unroll
    for (int s = 16; s > 0; s >>= 1) ev += __shfl_xor_sync(0xFFFFFFFFu, ev, s);

    if (lane < 4) {
        float lg = s_logit[seg_l][wis * 4 + lane];
        float trans = __expf(lg - m) / ev;
        float contrib = trans * s_att[seg_l] * ey;
        atomicAdd(&out[(size_t)eg * n_nodes + vjL], contrib);
    }
}

// ---------------------------------------------------------------------------
extern "C" void kernel_launch(void* const* d_in, const int* in_sizes, int n_in,
                              void* d_out, int out_size)
{
    const float* natt    = (const float*)d_in[0];
    const int*   edges   = (const int*)d_in[1];
    const float* edges_y = (const float*)d_in[2];
    const float* hu_in   = (const float*)d_in[3];   // [1, n_nodes, 256]
    const float* hc_in   = (const float*)d_in[4];   // [n_mem, 64]
    const float* Wc      = (const float*)d_in[5];
    const float* bc      = (const float*)d_in[6];
    const float* Wu      = (const float*)d_in[7];
    const float* bu      = (const float*)d_in[8];
    const float* rel_t   = (const float*)d_in[9];
    const float* ws      = (const float*)d_in[10];
    const float* fb      = (const float*)d_in[11];
    const float* ow      = (const float*)d_in[12];
    const float* ob      = (const float*)d_in[13];

    const int E       = in_sizes[2];
    const int n_nodes = in_sizes[3] / 256;
    const int n_mem   = in_sizes[4] / 64;
    const int n_seg   = E / 20;

    const int nb_c = (n_mem + 127) / 128;      // 1024
    const int nb_u = (n_nodes + 127) / 128;    // 391

    const int dyn_smem = (8704 + 2048) * 4;    // 43008 bytes
    cudaFuncSetAttribute(proj_both_kernel,
                         cudaFuncAttributeMaxDynamicSharedMemorySize, dyn_smem);

    cudaMemsetAsync(d_out, 0, (size_t)out_size * sizeof(float));

    proj_both_kernel<<<nb_c + nb_u, 256, dyn_smem>>>(
        hc_in, Wc, bc, n_mem, nb_c, hu_in, Wu, bu, n_nodes);

    edge_kernel<<<n_seg / 4, 640>>>(natt, edges, edges_y, rel_t, ws, fb, ow, ob,
                                    (float*)d_out, n_nodes);
}